// round 1
// baseline (speedup 1.0000x reference)
#include <cuda_runtime.h>
#include <math.h>

#define N_NODES 50000
#define N_EDGES 800000
#define N_GRAPHS 500
#define C 64
#define FE 16
#define NL 13
#define EPSBN 1e-5f

// ---------------- scratch (static device globals; no allocation) ----------------
__device__ float g_h[N_NODES * C];        // GEMM output per layer
__device__ float g_cur[N_NODES * C];      // current node features
__device__ float g_S[N_NODES * C];        // running skip sum
__device__ float g_coef[(size_t)NL * N_EDGES]; // ew, then ew*dis[src], CSR order
__device__ float g_dis[NL * N_NODES];     // 1/sqrt(deg) per layer per node
__device__ int   g_off[N_NODES + 1];
__device__ int   g_cnt[N_NODES];
__device__ int   g_csr_src[N_EDGES];
__device__ int   g_slot[N_EDGES];         // edge id -> CSR slot
__device__ float g_bnsum[2 * C];          // [sum | sumsq]
__device__ float g_mu[C], g_rstd[C];
__device__ float g_pool[N_GRAPHS * C];

// ---------------- CSR build ----------------
__global__ void k_hist(const int* __restrict__ dst) {
    int e = blockIdx.x * blockDim.x + threadIdx.x;
    if (e < N_EDGES) atomicAdd(&g_cnt[dst[e]], 1);
}

__global__ void k_scan() {
    __shared__ int sh[1024];
    int t = threadIdx.x;
    int run = 0;
    for (int base = 0; base < N_NODES; base += 1024) {
        int i = base + t;
        int v = (i < N_NODES) ? g_cnt[i] : 0;
        if (i < N_NODES) g_cnt[i] = 0;   // reset for scatter cursor
        sh[t] = v;
        __syncthreads();
        for (int d = 1; d < 1024; d <<= 1) {
            int x = (t >= d) ? sh[t - d] : 0;
            __syncthreads();
            sh[t] += x;
            __syncthreads();
        }
        if (i < N_NODES) g_off[i] = run + sh[t] - v;
        run += sh[1023];
        __syncthreads();
    }
    if (t == 0) g_off[N_NODES] = run;
}

__global__ void k_scatter(const int* __restrict__ src, const int* __restrict__ dst) {
    int e = blockIdx.x * blockDim.x + threadIdx.x;
    if (e >= N_EDGES) return;
    int d = dst[e];
    int pos = atomicAdd(&g_cnt[d], 1);
    int s = g_off[d] + pos;
    g_csr_src[s] = src[e];
    g_slot[e] = s;
}

// ---------------- edge MLP: all 13 layers' edge weights in one pass ----------------
__global__ __launch_bounds__(256) void k_edge_mlp(
    const float* __restrict__ attr,
    const float* __restrict__ m1W1, const float* __restrict__ m1b1,
    const float* __restrict__ m2W1, const float* __restrict__ m2b1,
    const float* __restrict__ hm1W, const float* __restrict__ hm1b,
    const float* __restrict__ hm2W, const float* __restrict__ hm2b)
{
    __shared__ float sWT[NL][FE][FE];  // [l][j][k] = W1[k][j]
    __shared__ float sb1[NL][FE];
    __shared__ float sw2[NL][FE];
    __shared__ float sb2[NL];
    int t = threadIdx.x;
    for (int i = t; i < NL * FE * FE; i += blockDim.x) {
        int l = i / (FE * FE), r = i % (FE * FE);
        int k = r / FE, j = r % FE;
        float w = (l == 0) ? m1W1[k * FE + j] : hm1W[(l - 1) * FE * FE + k * FE + j];
        sWT[l][j][k] = w;
    }
    for (int i = t; i < NL * FE; i += blockDim.x) {
        int l = i / FE, j = i % FE;
        sb1[l][j] = (l == 0) ? m1b1[j] : hm1b[(l - 1) * FE + j];
        sw2[l][j] = (l == 0) ? m2W1[j] : hm2W[(l - 1) * FE + j];
    }
    if (t < NL) sb2[t] = (t == 0) ? m2b1[0] : hm2b[t - 1];
    __syncthreads();

    int e = blockIdx.x * blockDim.x + t;
    if (e >= N_EDGES) return;

    float a[16];
    const float4* ap = (const float4*)(attr + (size_t)e * 16);
    float4 a0 = ap[0], a1 = ap[1], a2 = ap[2], a3 = ap[3];
    a[0]=a0.x; a[1]=a0.y; a[2]=a0.z; a[3]=a0.w;
    a[4]=a1.x; a[5]=a1.y; a[6]=a1.z; a[7]=a1.w;
    a[8]=a2.x; a[9]=a2.y; a[10]=a2.z; a[11]=a2.w;
    a[12]=a3.x; a[13]=a3.y; a[14]=a3.z; a[15]=a3.w;

    int slot = g_slot[e];
    #pragma unroll 1
    for (int l = 0; l < NL; l++) {
        float outv = 0.f;
        #pragma unroll
        for (int j = 0; j < FE; j++) {
            const float4* wp = (const float4*)&sWT[l][j][0];
            float4 w0 = wp[0], w1 = wp[1], w2 = wp[2], w3 = wp[3];
            float acc = sb1[l][j];
            acc += a[0]*w0.x + a[1]*w0.y + a[2]*w0.z + a[3]*w0.w;
            acc += a[4]*w1.x + a[5]*w1.y + a[6]*w1.z + a[7]*w1.w;
            acc += a[8]*w2.x + a[9]*w2.y + a[10]*w2.z + a[11]*w2.w;
            acc += a[12]*w3.x + a[13]*w3.y + a[14]*w3.z + a[15]*w3.w;
            outv += fmaxf(acc, 0.f) * sw2[l][j];
        }
        outv += sb2[l];
        float ew = 1.f / (1.f + __expf(-outv));
        g_coef[(size_t)l * N_EDGES + slot] = ew;
    }
}

// ---------------- degree -> dis = rsqrt(1 + sum(ew)) ----------------
__global__ void k_dis() {
    int i = blockIdx.x * blockDim.x + threadIdx.x;
    if (i >= NL * N_NODES) return;
    int l = i / N_NODES, n = i % N_NODES;
    int b = g_off[n], e2 = g_off[n + 1];
    const float* cw = g_coef + (size_t)l * N_EDGES;
    float d = 1.f;  // self loop weight 1
    for (int s = b; s < e2; s++) d += cw[s];
    g_dis[i] = rsqrtf(d);
}

// coef[l][slot] = ew * dis[l][src]
__global__ void k_coef() {
    int s = blockIdx.x * blockDim.x + threadIdx.x;
    if (s >= N_EDGES) return;
    int src = g_csr_src[s];
    #pragma unroll 1
    for (int l = 0; l < NL; l++)
        g_coef[(size_t)l * N_EDGES + s] *= g_dis[l * N_NODES + src];
}

// ---------------- BN stats over g_cur columns ----------------
__global__ void k_bnstats() {
    __shared__ float ssum[256], ssq[256];
    int c = threadIdx.x & 63;
    int rg = threadIdx.x >> 6;
    float s = 0.f, q = 0.f;
    for (int n = blockIdx.x * 4 + rg; n < N_NODES; n += gridDim.x * 4) {
        float v = g_cur[n * 64 + c];
        s += v; q += v * v;
    }
    ssum[threadIdx.x] = s; ssq[threadIdx.x] = q;
    __syncthreads();
    if (threadIdx.x < 64) {
        s = ssum[threadIdx.x] + ssum[threadIdx.x + 64] + ssum[threadIdx.x + 128] + ssum[threadIdx.x + 192];
        q = ssq[threadIdx.x] + ssq[threadIdx.x + 64] + ssq[threadIdx.x + 128] + ssq[threadIdx.x + 192];
        atomicAdd(&g_bnsum[c], s);
        atomicAdd(&g_bnsum[64 + c], q);
    }
}

__global__ void k_bnfinal() {
    int c = threadIdx.x;
    float mu = g_bnsum[c] * (1.f / N_NODES);
    float var = g_bnsum[64 + c] * (1.f / N_NODES) - mu * mu;
    g_mu[c] = mu;
    g_rstd[c] = rsqrtf(var + EPSBN);
}

// ---------------- GEMM: g_h = f(X) @ W, f = BN+ReLU for hidden layers ----------------
template <int BN>
__global__ __launch_bounds__(256) void k_gemm(const float* __restrict__ X,
                                              const float* __restrict__ W)
{
    __shared__ float sx[64][68];
    __shared__ float sw[64][68];
    __shared__ float smu[64], srs[64];
    int t = threadIdx.x;
    if (BN && t < 64) { smu[t] = g_mu[t]; srs[t] = g_rstd[t]; }
    for (int i = t; i < 1024; i += 256) {
        float4 v = ((const float4*)W)[i];
        int k = i >> 4, c4 = (i & 15) << 2;
        sw[k][c4] = v.x; sw[k][c4 + 1] = v.y; sw[k][c4 + 2] = v.z; sw[k][c4 + 3] = v.w;
    }
    __syncthreads();

    int row0 = blockIdx.x * 64;
    const float* Xp = BN ? g_cur : X;
    for (int i = t; i < 1024; i += 256) {
        int r = i >> 4, c4 = (i & 15) << 2;
        int n = row0 + r;
        float4 v = make_float4(0.f, 0.f, 0.f, 0.f);
        if (n < N_NODES) v = ((const float4*)(Xp + (size_t)n * 64))[i & 15];
        if (BN) {
            v.x = fmaxf((v.x - smu[c4]) * srs[c4], 0.f);
            v.y = fmaxf((v.y - smu[c4 + 1]) * srs[c4 + 1], 0.f);
            v.z = fmaxf((v.z - smu[c4 + 2]) * srs[c4 + 2], 0.f);
            v.w = fmaxf((v.w - smu[c4 + 3]) * srs[c4 + 3], 0.f);
        }
        sx[r][c4] = v.x; sx[r][c4 + 1] = v.y; sx[r][c4 + 2] = v.z; sx[r][c4 + 3] = v.w;
    }
    __syncthreads();

    int c2 = t & 15;   // column group (4 cols)
    int rg = t >> 4;   // row group (4 rows)
    float acc[4][4] = {};
    #pragma unroll 8
    for (int k = 0; k < 64; k++) {
        float4 b = *(const float4*)&sw[k][c2 << 2];
        float a0 = sx[(rg << 2) + 0][k];
        float a1 = sx[(rg << 2) + 1][k];
        float a2 = sx[(rg << 2) + 2][k];
        float a3 = sx[(rg << 2) + 3][k];
        acc[0][0] += a0 * b.x; acc[0][1] += a0 * b.y; acc[0][2] += a0 * b.z; acc[0][3] += a0 * b.w;
        acc[1][0] += a1 * b.x; acc[1][1] += a1 * b.y; acc[1][2] += a1 * b.z; acc[1][3] += a1 * b.w;
        acc[2][0] += a2 * b.x; acc[2][1] += a2 * b.y; acc[2][2] += a2 * b.z; acc[2][3] += a2 * b.w;
        acc[3][0] += a3 * b.x; acc[3][1] += a3 * b.y; acc[3][2] += a3 * b.z; acc[3][3] += a3 * b.w;
    }
    #pragma unroll
    for (int i = 0; i < 4; i++) {
        int n = row0 + (rg << 2) + i;
        if (n < N_NODES)
            ((float4*)(g_h + (size_t)n * 64))[c2] =
                make_float4(acc[i][0], acc[i][1], acc[i][2], acc[i][3]);
    }
}

// ---------------- aggregation: g_cur[n] = dis[n]*sum(coef*h[src]) + dis[n]^2*h[n] + bias ----------------
__global__ __launch_bounds__(256) void k_agg(int l, const float* __restrict__ bias) {
    int w = (blockIdx.x * blockDim.x + threadIdx.x) >> 5;
    int lane = threadIdx.x & 31;
    if (w >= N_NODES) return;
    int n = w;
    int b = g_off[n], e2 = g_off[n + 1];
    const float* __restrict__ cf = g_coef + (size_t)l * N_EDGES;
    float2 acc = make_float2(0.f, 0.f);
    int s = b;
    // unrolled by 2 for a bit of MLP
    for (; s + 1 < e2; s += 2) {
        int s0 = g_csr_src[s], s1 = g_csr_src[s + 1];
        float w0 = cf[s], w1 = cf[s + 1];
        float2 h0 = ((const float2*)(g_h + (size_t)s0 * 64))[lane];
        float2 h1 = ((const float2*)(g_h + (size_t)s1 * 64))[lane];
        acc.x += w0 * h0.x + w1 * h1.x;
        acc.y += w0 * h0.y + w1 * h1.y;
    }
    if (s < e2) {
        int s0 = g_csr_src[s];
        float w0 = cf[s];
        float2 h0 = ((const float2*)(g_h + (size_t)s0 * 64))[lane];
        acc.x += w0 * h0.x;
        acc.y += w0 * h0.y;
    }
    float dn = g_dis[l * N_NODES + n];
    float2 hs = ((const float2*)(g_h + (size_t)n * 64))[lane];
    float2 bb = ((const float2*)bias)[lane];
    float2 o;
    o.x = dn * acc.x + dn * dn * hs.x + bb.x;
    o.y = dn * acc.y + dn * dn * hs.y + bb.y;
    ((float2*)(g_cur + (size_t)n * 64))[lane] = o;
}

// ---------------- skips, pool, head ----------------
__global__ void k_copyS() {
    int i = blockIdx.x * blockDim.x + threadIdx.x;
    if (i < N_NODES * C) g_S[i] = g_cur[i];
}

__global__ void k_skip() {
    int i = blockIdx.x * blockDim.x + threadIdx.x;
    if (i >= N_NODES * C) return;
    float c = g_cur[i] + g_S[i];
    g_cur[i] = c;
    g_S[i] += c;
}

__global__ void k_pool(const int* __restrict__ batch) {
    int i = blockIdx.x * blockDim.x + threadIdx.x;
    if (i >= N_NODES * C) return;
    int n = i >> 6, c = i & 63;
    float v = fmaxf(g_cur[i], 0.f);  // relu; non-negative -> uint-ordered
    atomicMax((unsigned int*)&g_pool[batch[n] * 64 + c], __float_as_uint(v));
}

__global__ void k_out(const float* __restrict__ linW, const float* __restrict__ linb,
                      float* __restrict__ out) {
    int i = blockIdx.x * blockDim.x + threadIdx.x;
    if (i >= N_GRAPHS * 2) return;
    int g = i >> 1, cls = i & 1;
    float s = linb[cls];
    #pragma unroll 8
    for (int k = 0; k < 64; k++) s += g_pool[g * 64 + k] * linW[k * 2 + cls];
    out[i] = s;
}

// ---------------- orchestration ----------------
extern "C" void kernel_launch(void* const* d_in, const int* in_sizes, int n_in,
                              void* d_out, int out_size) {
    const float* x     = (const float*)d_in[0];
    const int*   ei    = (const int*)d_in[1];
    const int*   batch = (const int*)d_in[2];
    // d_in[3] = dropout (unused, eval mode)
    const float* attr  = (const float*)d_in[4];
    const float* Wlin1 = (const float*)d_in[5];
    const float* bias1 = (const float*)d_in[6];
    const float* m1W1  = (const float*)d_in[7];
    const float* m1b1  = (const float*)d_in[8];
    const float* m2W1  = (const float*)d_in[9];
    const float* m2b1  = (const float*)d_in[10];
    const float* hWlin = (const float*)d_in[11];
    const float* hbias = (const float*)d_in[12];
    const float* hm1W  = (const float*)d_in[13];
    const float* hm1b  = (const float*)d_in[14];
    const float* hm2W  = (const float*)d_in[15];
    const float* hm2b  = (const float*)d_in[16];
    const float* linW  = (const float*)d_in[17];
    const float* linb  = (const float*)d_in[18];
    (void)in_sizes; (void)n_in; (void)out_size;

    const int* src = ei;
    const int* dst = ei + N_EDGES;

    void *p_cnt, *p_bn, *p_pool;
    cudaGetSymbolAddress(&p_cnt, g_cnt);
    cudaGetSymbolAddress(&p_bn, g_bnsum);
    cudaGetSymbolAddress(&p_pool, g_pool);

    // CSR build (by dst)
    cudaMemsetAsync(p_cnt, 0, N_NODES * sizeof(int));
    k_hist<<<(N_EDGES + 255) / 256, 256>>>(dst);
    k_scan<<<1, 1024>>>();
    k_scatter<<<(N_EDGES + 255) / 256, 256>>>(src, dst);

    // edge weights for all 13 layers, then normalization coefficients
    k_edge_mlp<<<(N_EDGES + 255) / 256, 256>>>(attr, m1W1, m1b1, m2W1, m2b1,
                                               hm1W, hm1b, hm2W, hm2b);
    k_dis<<<(NL * N_NODES + 255) / 256, 256>>>();
    k_coef<<<(N_EDGES + 255) / 256, 256>>>();

    const int gemm_blocks = (N_NODES + 63) / 64;
    const int agg_blocks = (N_NODES * 32 + 255) / 256;
    const int ew_blocks = (N_NODES * C + 255) / 256;

    // layer 0 (conv1): no BN, input = x
    k_gemm<0><<<gemm_blocks, 256>>>(x, Wlin1);
    k_agg<<<agg_blocks, 256>>>(0, bias1);
    k_copyS<<<ew_blocks, 256>>>();

    // 12 hidden layers, skip after every 2
    for (int l = 1; l <= 12; l++) {
        cudaMemsetAsync(p_bn, 0, 2 * C * sizeof(float));
        k_bnstats<<<512, 256>>>();
        k_bnfinal<<<1, 64>>>();
        k_gemm<1><<<gemm_blocks, 256>>>(nullptr, hWlin + (size_t)(l - 1) * C * C);
        k_agg<<<agg_blocks, 256>>>(l, hbias + (size_t)(l - 1) * C);
        if ((l & 1) == 0) k_skip<<<ew_blocks, 256>>>();
    }

    // relu -> per-graph max pool -> linear head
    cudaMemsetAsync(p_pool, 0, N_GRAPHS * C * sizeof(float));
    k_pool<<<ew_blocks, 256>>>(batch);
    k_out<<<(N_GRAPHS * 2 + 255) / 256, 256>>>(linW, linb, (float*)d_out);
}

// round 6
// speedup vs baseline: 1.2272x; 1.2272x over previous
#include <cuda_runtime.h>
#include <math.h>

#define N_NODES 50000
#define N_EDGES 800000
#define N_GRAPHS 500
#define C 64
#define FE 16
#define NL 13
#define EPSBN 1e-5f
#define NCHUNK 49   // ceil(50000/1024)

typedef unsigned long long ull;

static __device__ __forceinline__ ull d_pack2(float lo, float hi) {
    ull r; asm("mov.b64 %0,{%1,%2};" : "=l"(r) : "f"(lo), "f"(hi)); return r;
}
static __device__ __forceinline__ void d_unpack2(ull v, float& lo, float& hi) {
    asm("mov.b64 {%0,%1},%2;" : "=f"(lo), "=f"(hi) : "l"(v));
}
static __device__ __forceinline__ ull d_fma2(ull a, ull b, ull c) {
    ull d; asm("fma.rn.f32x2 %0,%1,%2,%3;" : "=l"(d) : "l"(a), "l"(b), "l"(c)); return d;
}

// ---------------- scratch ----------------
__device__ float g_h[N_NODES * C];
__device__ float g_cur[N_NODES * C];
__device__ float g_S[N_NODES * C];
__device__ float g_coef[(size_t)NL * N_EDGES];   // raw sigmoid edge weights, CSR order
__device__ float g_dis[NL * N_NODES];
__device__ int   g_off[N_NODES + 1];
__device__ int   g_cnt[N_NODES];
__device__ int   g_csr_src[N_EDGES];
__device__ int   g_slot[N_EDGES];
__device__ float g_bn[256];                      // two ping-pong stat buffers of 128
__device__ float g_pool[N_GRAPHS * C];
__device__ int   g_chunk[64];
__device__ int   g_choff[64];

// ---------------- CSR build ----------------
__global__ void k_hist(const int* __restrict__ dst) {
    int e = blockIdx.x * blockDim.x + threadIdx.x;
    if (e < N_EDGES) atomicAdd(&g_cnt[dst[e]], 1);
}

__global__ void k_scan1() {
    __shared__ int sh[1024];
    int b = blockIdx.x, t = threadIdx.x;
    int i = b * 1024 + t;
    int v = (i < N_NODES) ? g_cnt[i] : 0;
    if (i < N_NODES) g_cnt[i] = 0;   // reset scatter cursor
    sh[t] = v;
    __syncthreads();
    for (int d = 1; d < 1024; d <<= 1) {
        int x = (t >= d) ? sh[t - d] : 0;
        __syncthreads();
        sh[t] += x;
        __syncthreads();
    }
    if (i < N_NODES) g_off[i] = sh[t] - v;  // local exclusive
    if (t == 1023) g_chunk[b] = sh[1023];
}

__global__ void k_scan2() {
    __shared__ int sh[64];
    int t = threadIdx.x;
    int v = (t < NCHUNK) ? g_chunk[t] : 0;
    sh[t] = v;
    __syncthreads();
    for (int d = 1; d < 64; d <<= 1) {
        int x = (t >= d) ? sh[t - d] : 0;
        __syncthreads();
        sh[t] += x;
        __syncthreads();
    }
    if (t < NCHUNK) g_choff[t] = sh[t] - v;
    if (t == 63) g_off[N_NODES] = sh[63];
}

__global__ void k_scan3() {
    int i = blockIdx.x * blockDim.x + threadIdx.x;
    if (i < N_NODES) g_off[i] += g_choff[i >> 10];
}

__global__ void k_scatter(const int* __restrict__ src, const int* __restrict__ dst) {
    int e = blockIdx.x * blockDim.x + threadIdx.x;
    if (e >= N_EDGES) return;
    int d = dst[e];
    int pos = atomicAdd(&g_cnt[d], 1);
    int s = g_off[d] + pos;
    g_csr_src[s] = src[e];
    g_slot[e] = s;
}

// ---------------- edge MLP: 13 layers, 4 edges/thread, f32x2 packed ----------------
#define EPT 4
__global__ __launch_bounds__(256) void k_edge_mlp(
    const float* __restrict__ attr,
    const float* __restrict__ m1W1, const float* __restrict__ m1b1,
    const float* __restrict__ m2W1, const float* __restrict__ m2b1,
    const float* __restrict__ hm1W, const float* __restrict__ hm1b,
    const float* __restrict__ hm2W, const float* __restrict__ hm2b)
{
    __shared__ ull   sW[NL][FE][FE];   // dup-packed W1^T: [l][j][k] = (w,w)
    __shared__ ull   sb1d[NL][FE];     // dup-packed bias1
    __shared__ float sw2[NL][FE];
    __shared__ float sb2v[NL];
    int t = threadIdx.x;
    for (int i = t; i < NL * FE * FE; i += 256) {
        int l = i / (FE * FE), r = i % (FE * FE);
        int k = r / FE, j = r % FE;
        float w = (l == 0) ? m1W1[k * FE + j] : hm1W[(l - 1) * FE * FE + k * FE + j];
        sW[l][j][k] = d_pack2(w, w);
    }
    for (int i = t; i < NL * FE; i += 256) {
        int l = i / FE, j = i % FE;
        float b = (l == 0) ? m1b1[j] : hm1b[(l - 1) * FE + j];
        sb1d[l][j] = d_pack2(b, b);
        sw2[l][j] = (l == 0) ? m2W1[j] : hm2W[(l - 1) * FE + j];
    }
    if (t < NL) sb2v[t] = (t == 0) ? m2b1[0] : hm2b[t - 1];
    __syncthreads();

    int base = blockIdx.x * (256 * EPT) + t;
    bool val[EPT];
    int sl[EPT];
    float a[EPT][16];
    #pragma unroll
    for (int j = 0; j < EPT; j++) {
        int e = base + j * 256;
        val[j] = (e < N_EDGES);
        int es = val[j] ? e : 0;
        sl[j] = val[j] ? g_slot[e] : 0;
        const float4* ap = (const float4*)(attr + (size_t)es * 16);
        float4 a0 = ap[0], a1 = ap[1], a2 = ap[2], a3 = ap[3];
        a[j][0]=a0.x; a[j][1]=a0.y; a[j][2]=a0.z; a[j][3]=a0.w;
        a[j][4]=a1.x; a[j][5]=a1.y; a[j][6]=a1.z; a[j][7]=a1.w;
        a[j][8]=a2.x; a[j][9]=a2.y; a[j][10]=a2.z; a[j][11]=a2.w;
        a[j][12]=a3.x; a[j][13]=a3.y; a[j][14]=a3.z; a[j][15]=a3.w;
    }
    ull ap0[16], ap1[16];
    #pragma unroll
    for (int k = 0; k < 16; k++) {
        ap0[k] = d_pack2(a[0][k], a[1][k]);
        ap1[k] = d_pack2(a[2][k], a[3][k]);
    }

    #pragma unroll 1
    for (int l = 0; l < NL; l++) {
        float out0 = 0.f, out1 = 0.f, out2 = 0.f, out3 = 0.f;
        #pragma unroll
        for (int jj = 0; jj < FE; jj++) {
            ull acc0 = sb1d[l][jj], acc1 = acc0;
            const ulonglong2* wp = (const ulonglong2*)&sW[l][jj][0];
            #pragma unroll
            for (int kk = 0; kk < 8; kk++) {
                ulonglong2 wv = wp[kk];
                acc0 = d_fma2(ap0[2 * kk],     wv.x, acc0);
                acc0 = d_fma2(ap0[2 * kk + 1], wv.y, acc0);
                acc1 = d_fma2(ap1[2 * kk],     wv.x, acc1);
                acc1 = d_fma2(ap1[2 * kk + 1], wv.y, acc1);
            }
            float h0, h1, h2, h3;
            d_unpack2(acc0, h0, h1);
            d_unpack2(acc1, h2, h3);
            float w2s = sw2[l][jj];
            out0 += fmaxf(h0, 0.f) * w2s;
            out1 += fmaxf(h1, 0.f) * w2s;
            out2 += fmaxf(h2, 0.f) * w2s;
            out3 += fmaxf(h3, 0.f) * w2s;
        }
        float b2 = sb2v[l];
        float o[EPT] = {out0 + b2, out1 + b2, out2 + b2, out3 + b2};
        float* cf = g_coef + (size_t)l * N_EDGES;
        #pragma unroll
        for (int j = 0; j < EPT; j++)
            if (val[j]) cf[sl[j]] = 1.f / (1.f + __expf(-o[j]));
    }
}

// ---------------- dis = rsqrt(1 + sum ew) ; also zero pool ----------------
__global__ void k_dis() {
    int i = blockIdx.x * blockDim.x + threadIdx.x;
    if (i < N_GRAPHS * C) g_pool[i] = 0.f;
    if (i >= NL * N_NODES) return;
    int l = i / N_NODES, n = i % N_NODES;
    int b = g_off[n], e2 = g_off[n + 1];
    const float* cw = g_coef + (size_t)l * N_EDGES;
    float d0 = 1.f, d1 = 0.f, d2 = 0.f, d3 = 0.f;
    int s = b;
    for (; s + 3 < e2; s += 4) { d0 += cw[s]; d1 += cw[s+1]; d2 += cw[s+2]; d3 += cw[s+3]; }
    for (; s < e2; s++) d0 += cw[s];
    g_dis[i] = rsqrtf(d0 + d1 + d2 + d3);
}

// ---------------- GEMM: g_h = f(X) @ W  (f32x2 packed) ----------------
template <int BN>
__global__ __launch_bounds__(256) void k_gemm(const float* __restrict__ X,
                                              const float* __restrict__ W,
                                              int rbuf, int zbuf)
{
    __shared__ ull   sxd[64][64];   // dup-packed activations [row][k]
    __shared__ float sw[64][64];    // W [k][col]
    int t = threadIdx.x;

    for (int i = t; i < 1024; i += 256) {
        float4 v = ((const float4*)W)[i];
        int k = i >> 4, c4 = (i & 15) << 2;
        sw[k][c4] = v.x; sw[k][c4 + 1] = v.y; sw[k][c4 + 2] = v.z; sw[k][c4 + 3] = v.w;
    }

    float mu[4], rs[4];
    if (BN) {
        const float* sb = g_bn + rbuf;
        int k0 = (t & 15) << 2;
        #pragma unroll
        for (int u = 0; u < 4; u++) {
            float s = sb[k0 + u], q = sb[64 + k0 + u];
            float m = s * (1.f / N_NODES);
            float var = q * (1.f / N_NODES) - m * m;
            mu[u] = m; rs[u] = rsqrtf(var + EPSBN);
        }
    }

    int row0 = blockIdx.x * 64;
    const float* Xp = BN ? g_cur : X;
    for (int i = t; i < 1024; i += 256) {
        int r = i >> 4, c4g = i & 15;
        int n = row0 + r;
        float4 v = make_float4(0.f, 0.f, 0.f, 0.f);
        if (n < N_NODES) v = ((const float4*)(Xp + (size_t)n * 64))[c4g];
        if (BN) {
            v.x = fmaxf((v.x - mu[0]) * rs[0], 0.f);
            v.y = fmaxf((v.y - mu[1]) * rs[1], 0.f);
            v.z = fmaxf((v.z - mu[2]) * rs[2], 0.f);
            v.w = fmaxf((v.w - mu[3]) * rs[3], 0.f);
        }
        int kb = c4g << 2;
        sxd[r][kb]     = d_pack2(v.x, v.x);
        sxd[r][kb + 1] = d_pack2(v.y, v.y);
        sxd[r][kb + 2] = d_pack2(v.z, v.z);
        sxd[r][kb + 3] = d_pack2(v.w, v.w);
    }
    if (blockIdx.x == 0 && t < 128) g_bn[zbuf + t] = 0.f;  // zero stats buf for this layer's agg
    __syncthreads();

    int c2 = t & 15, rg = t >> 4;
    ull acc[4][2];
    #pragma unroll
    for (int i2 = 0; i2 < 4; i2++) { acc[i2][0] = 0ull; acc[i2][1] = 0ull; }

    #pragma unroll 16
    for (int k = 0; k < 64; k++) {
        ulonglong2 b2 = *(const ulonglong2*)&sw[k][c2 << 2];
        #pragma unroll
        for (int i2 = 0; i2 < 4; i2++) {
            ull av = sxd[(rg << 2) + i2][k];
            acc[i2][0] = d_fma2(av, b2.x, acc[i2][0]);
            acc[i2][1] = d_fma2(av, b2.y, acc[i2][1]);
        }
    }
    #pragma unroll
    for (int i2 = 0; i2 < 4; i2++) {
        int n = row0 + (rg << 2) + i2;
        if (n < N_NODES) {
            float x0, x1, x2, x3;
            d_unpack2(acc[i2][0], x0, x1);
            d_unpack2(acc[i2][1], x2, x3);
            ((float4*)(g_h + (size_t)n * 64))[c2] = make_float4(x0, x1, x2, x3);
        }
    }
}

// ---------------- aggregation + fused epilogues ----------------
// MODE bits: 1=init S, 2=add skip, 4=BN stats, 8=relu+pool (final)
template <int MODE>
__global__ __launch_bounds__(256) void k_agg(int l, const float* __restrict__ bias,
                                             const int* __restrict__ batch)
{
    __shared__ float s_red[128];
    if (MODE & 4) {
        if (threadIdx.x < 128) s_red[threadIdx.x] = 0.f;
        __syncthreads();
    }
    int n = (blockIdx.x * 256 + threadIdx.x) >> 5;
    int lane = threadIdx.x & 31;
    int b = g_off[n], e2 = g_off[n + 1];
    const float* __restrict__ cf = g_coef + (size_t)l * N_EDGES;
    const float* __restrict__ disl = g_dis + l * N_NODES;
    float2 acc = make_float2(0.f, 0.f);
    int s = b;
    for (; s + 3 < e2; s += 4) {
        int i0 = g_csr_src[s], i1 = g_csr_src[s + 1], i2 = g_csr_src[s + 2], i3 = g_csr_src[s + 3];
        float w0 = cf[s] * disl[i0], w1 = cf[s + 1] * disl[i1];
        float w2 = cf[s + 2] * disl[i2], w3 = cf[s + 3] * disl[i3];
        float2 h0 = ((const float2*)(g_h + (size_t)i0 * 64))[lane];
        float2 h1 = ((const float2*)(g_h + (size_t)i1 * 64))[lane];
        float2 h2 = ((const float2*)(g_h + (size_t)i2 * 64))[lane];
        float2 h3 = ((const float2*)(g_h + (size_t)i3 * 64))[lane];
        acc.x += w0 * h0.x + w1 * h1.x + w2 * h2.x + w3 * h3.x;
        acc.y += w0 * h0.y + w1 * h1.y + w2 * h2.y + w3 * h3.y;
    }
    for (; s < e2; s++) {
        int i0 = g_csr_src[s];
        float w0 = cf[s] * disl[i0];
        float2 h0 = ((const float2*)(g_h + (size_t)i0 * 64))[lane];
        acc.x += w0 * h0.x;
        acc.y += w0 * h0.y;
    }
    float dn = disl[n];
    float2 hs = ((const float2*)(g_h + (size_t)n * 64))[lane];
    float2 bb = ((const float2*)bias)[lane];
    float2 c;
    c.x = dn * acc.x + dn * dn * hs.x + bb.x;
    c.y = dn * acc.y + dn * dn * hs.y + bb.y;

    if (MODE & 2) {
        float2 Sv = ((const float2*)(g_S + (size_t)n * 64))[lane];
        c.x += Sv.x; c.y += Sv.y;
        if (!(MODE & 8))
            ((float2*)(g_S + (size_t)n * 64))[lane] = make_float2(Sv.x + c.x, Sv.y + c.y);
    }
    if (MODE & 1)
        ((float2*)(g_S + (size_t)n * 64))[lane] = c;
    if (!(MODE & 8))
        ((float2*)(g_cur + (size_t)n * 64))[lane] = c;
    if (MODE & 8) {
        int g = batch[n];
        atomicMax((unsigned int*)&g_pool[g * 64 + 2 * lane],     __float_as_uint(fmaxf(c.x, 0.f)));
        atomicMax((unsigned int*)&g_pool[g * 64 + 2 * lane + 1], __float_as_uint(fmaxf(c.y, 0.f)));
    }
    if (MODE & 4) {
        atomicAdd(&s_red[2 * lane],     c.x);
        atomicAdd(&s_red[2 * lane + 1], c.y);
        atomicAdd(&s_red[64 + 2 * lane],     c.x * c.x);
        atomicAdd(&s_red[64 + 2 * lane + 1], c.y * c.y);
        __syncthreads();
        if (threadIdx.x < 128)
            atomicAdd(&g_bn[128 * (l & 1) + threadIdx.x], s_red[threadIdx.x]);
    }
}

// ---------------- head ----------------
__global__ void k_out(const float* __restrict__ linW, const float* __restrict__ linb,
                      float* __restrict__ out) {
    int i = blockIdx.x * blockDim.x + threadIdx.x;
    if (i >= N_GRAPHS * 2) return;
    int g = i >> 1, cls = i & 1;
    float sacc = linb[cls];
    #pragma unroll 8
    for (int k = 0; k < 64; k++) sacc += g_pool[g * 64 + k] * linW[k * 2 + cls];
    out[i] = sacc;
}

// ---------------- orchestration ----------------
extern "C" void kernel_launch(void* const* d_in, const int* in_sizes, int n_in,
                              void* d_out, int out_size) {
    const float* x     = (const float*)d_in[0];
    const int*   ei    = (const int*)d_in[1];
    const int*   batch = (const int*)d_in[2];
    const float* attr  = (const float*)d_in[4];
    const float* Wlin1 = (const float*)d_in[5];
    const float* bias1 = (const float*)d_in[6];
    const float* m1W1  = (const float*)d_in[7];
    const float* m1b1  = (const float*)d_in[8];
    const float* m2W1  = (const float*)d_in[9];
    const float* m2b1  = (const float*)d_in[10];
    const float* hWlin = (const float*)d_in[11];
    const float* hbias = (const float*)d_in[12];
    const float* hm1W  = (const float*)d_in[13];
    const float* hm1b  = (const float*)d_in[14];
    const float* hm2W  = (const float*)d_in[15];
    const float* hm2b  = (const float*)d_in[16];
    const float* linW  = (const float*)d_in[17];
    const float* linb  = (const float*)d_in[18];
    (void)in_sizes; (void)n_in; (void)out_size;

    const int* src = ei;
    const int* dst = ei + N_EDGES;

    void* p_cnt;
    cudaGetSymbolAddress(&p_cnt, g_cnt);

    // CSR by dst
    cudaMemsetAsync(p_cnt, 0, N_NODES * sizeof(int));
    k_hist<<<(N_EDGES + 255) / 256, 256>>>(dst);
    k_scan1<<<NCHUNK, 1024>>>();
    k_scan2<<<1, 64>>>();
    k_scan3<<<(N_NODES + 255) / 256, 256>>>();
    k_scatter<<<(N_EDGES + 255) / 256, 256>>>(src, dst);

    // edge weights (all 13 layers) + per-layer node norms (also zeroes pool)
    k_edge_mlp<<<(N_EDGES + 256 * EPT - 1) / (256 * EPT), 256>>>(
        attr, m1W1, m1b1, m2W1, m2b1, hm1W, hm1b, hm2W, hm2b);
    k_dis<<<(NL * N_NODES + 255) / 256, 256>>>();

    const int gemm_blocks = (N_NODES + 63) / 64;
    const int agg_blocks = N_NODES / 8;   // 6250, exact

    // layer 0: no BN; init S; stats for layer 1
    k_gemm<0><<<gemm_blocks, 256>>>(x, Wlin1, 0, 0);
    k_agg<5><<<agg_blocks, 256>>>(0, bias1, batch);

    // hidden layers 1..11
    for (int l = 1; l <= 11; l++) {
        k_gemm<1><<<gemm_blocks, 256>>>(nullptr, hWlin + (size_t)(l - 1) * C * C,
                                        128 * ((l - 1) & 1), 128 * (l & 1));
        if (l & 1)
            k_agg<4><<<agg_blocks, 256>>>(l, hbias + (size_t)(l - 1) * C, batch);
        else
            k_agg<6><<<agg_blocks, 256>>>(l, hbias + (size_t)(l - 1) * C, batch);
    }
    // layer 12: skip + relu + pool, no stats
    k_gemm<1><<<gemm_blocks, 256>>>(nullptr, hWlin + (size_t)11 * C * C, 128, 0);
    k_agg<10><<<agg_blocks, 256>>>(12, hbias + (size_t)11 * C, batch);

    k_out<<<(N_GRAPHS * 2 + 255) / 256, 256>>>(linW, linb, (float*)d_out);
}